// round 10
// baseline (speedup 1.0000x reference)
#include <cuda_runtime.h>
#include <math.h>
#include <stdint.h>

#define B_  512
#define XD  768
#define YD  128
#define H2_ 512
#define NPART 16
#define KS1 4          // gemm1 K-split (768/4 = 192)
#define KS2 8          // gemm2 K-split (512/8 = 64)

typedef unsigned long long u64;

__device__ float  g_H[2][KS1][B_ * H2_];   // gemm1 raw partials
__device__ float  g_Q[2][KS2][B_ * YD];    // gemm2 raw partials
__device__ double g_SyP [NPART][YD];
__device__ double g_Sy2P[NPART][YD];
__device__ double g_pos_row[B_];
__device__ double g_all_row[B_];
__device__ unsigned int g_ctr = 0;

// ---------------- tf32 helpers ----------------
__device__ __forceinline__ float tf32r(float x) {
    float r; asm("cvt.rna.tf32.f32 %0, %1;" : "=f"(r) : "f"(x)); return r;
}
// D += A(16x8) * B(8x8), tf32 inputs, f32 accum
#define MMA8(c, A, B) \
    asm volatile("mma.sync.aligned.m16n8k8.row.col.f32.tf32.tf32.f32 " \
        "{%0,%1,%2,%3},{%4,%5,%6,%7},{%8,%9},{%0,%1,%2,%3};" \
        : "+f"((c)[0]), "+f"((c)[1]), "+f"((c)[2]), "+f"((c)[3]) \
        : "r"((A)[0]), "r"((A)[1]), "r"((A)[2]), "r"((A)[3]), \
          "r"((B)[0]), "r"((B)[1]))

// ---------------------------------------------------------------------------
// Kernel A: blocks 0..127 = GEMM1 partials via 3xTF32 HMMA.
//           blocks 128..143 = y column stats.
// Block: 128x128 tile, K=192 slice, 12 chunks of BK=16, **512 thr, 16 warps**
// (4M x 4N, warp tile 32x32). Double-buffered, one sync per chunk.
// ---------------------------------------------------------------------------
__global__ __launch_bounds__(512) void k_gemm1_mma(
    const float* __restrict__ X, const float* __restrict__ Y,
    const float* __restrict__ Wmu, const float* __restrict__ Wlv)
{
    const int b = blockIdx.x;
    if (b >= 128) {
        const int p = b - 128;
        const int d = threadIdx.x;
        if (d < YD) {
            const int j0 = p * (B_ / NPART);
            double sy0 = 0, sy1 = 0, s20 = 0, s21 = 0;
            #pragma unroll 4
            for (int j = j0; j < j0 + B_ / NPART; j += 2) {
                double v0 = (double)Y[j * YD + d], v1 = (double)Y[(j + 1) * YD + d];
                sy0 += v0; s20 = fma(v0, v0, s20);
                sy1 += v1; s21 = fma(v1, v1, s21);
            }
            g_SyP[p][d] = sy0 + sy1; g_Sy2P[p][d] = s20 + s21;
        }
        return;
    }

    // dynamic smem: Ah | Al | Bh | Bl, each double-buffered (16KB each)
    extern __shared__ float smem[];
    float* Ah = smem;                 // [2][2][8][32][4]
    float* Al = smem + 4096;
    float* Bh = smem + 8192;          // [2][2][16][32][2]
    float* Bl = smem + 12288;

    const int head = b & 1;
    const int ks   = (b >> 1) & 3;
    const int t4   = b >> 3;               // 0..15
    const int m0   = (t4 >> 2) * 128;
    const int n0   = (t4 & 3) * 128;
    const int kb   = ks * 192;
    const float* W = head ? Wlv : Wmu;
    float* P       = &g_H[head][ks][0];

    const int tid  = threadIdx.x;
    const int wid  = tid >> 5;
    const int lane = tid & 31;
    const int wm   = wid >> 2;             // 0..3 (32-row band)
    const int wn   = wid & 3;              // 0..3 (32-col band)
    const int lg   = lane >> 2;
    const int lt   = lane & 3;

    // A loader: ar = tid>>2 (0..127), akq = tid&3 -> k = akq*4 + 0..3
    const int ar = tid >> 2, akq = tid & 3;
    const int akst = akq >> 1, akh = akq & 1;
    const int amt = ar >> 4, ag = ar & 7, arh = (ar >> 3) & 1;
    const float* Xp = X + (size_t)(m0 + ar) * XD + kb + akq * 4;
    // B loader: bkr = tid>>5 (0..15), bn = tid&31 -> n = bn*4 + 0..3
    const int bkr = tid >> 5, bn = tid & 31;
    const int bt  = bkr & 3, bkh = (bkr >> 2) & 1, bkst = bkr >> 3;
    const int bnt = bn >> 1, bg0 = (bn & 1) * 4;
    const float* Wp = W + (size_t)(kb + bkr) * H2_ + n0 + bn * 4;

    float acc[2][4][4] = {};
    float4 xa, wb;

    #define G1_LOAD(ch) do { \
        xa = *(const float4*)(Xp + (ch) * 16); \
        wb = *(const float4*)(Wp + (size_t)(ch) * 16 * H2_); \
    } while (0)

    #define G1_STAGE(bf) do { \
        { \
            float e[4] = {xa.x, xa.y, xa.z, xa.w}; \
            _Pragma("unroll") \
            for (int q = 0; q < 4; q++) { \
                float hi = tf32r(e[q]), lo = e[q] - hi; \
                int lam = (ag * 4 + q) ^ (akst | (ag & 2)); \
                int idx = (((((bf) * 2 + akst) * 8 + amt) * 32 + lam) * 4) + (arh + 2 * akh); \
                Ah[idx] = hi; Al[idx] = lo; \
            } \
        } \
        { \
            float f[4] = {wb.x, wb.y, wb.z, wb.w}; \
            _Pragma("unroll") \
            for (int q = 0; q < 4; q++) { \
                float hi = tf32r(f[q]), lo = f[q] - hi; \
                int g0  = bg0 + q; \
                int lam = (g0 * 4 + bt) ^ (bnt & 15); \
                int idx = (((((bf) * 2 + bkst) * 16 + bnt) * 32 + lam) * 2) + bkh; \
                Bh[idx] = hi; Bl[idx] = lo; \
            } \
        } \
    } while (0)

    // prologue
    G1_LOAD(0);
    G1_STAGE(0);
    G1_LOAD(1);
    __syncthreads();

    for (int ch = 0; ch < 12; ch++) {
        const int bfc = ch & 1;
        if (ch + 1 < 12) G1_STAGE((ch + 1) & 1);
        if (ch + 2 < 12) G1_LOAD(ch + 2);

        #pragma unroll
        for (int kst = 0; kst < 2; kst++) {
            uint32_t Af[2][4], Afl[2][4];
            #pragma unroll
            for (int mf = 0; mf < 2; mf++) {
                int mt  = wm * 2 + mf;
                int lam = lane ^ (kst | ((lane >> 2) & 2));
                int idx = (((bfc * 2 + kst) * 8 + mt) * 32 + lam) * 4;
                uint4 h = *(const uint4*)&Ah[idx];
                uint4 l = *(const uint4*)&Al[idx];
                Af [mf][0] = h.x; Af [mf][1] = h.y; Af [mf][2] = h.z; Af [mf][3] = h.w;
                Afl[mf][0] = l.x; Afl[mf][1] = l.y; Afl[mf][2] = l.z; Afl[mf][3] = l.w;
            }
            uint32_t Bf[4][2], Bfl[4][2];
            #pragma unroll
            for (int nf = 0; nf < 4; nf++) {
                int nt  = wn * 4 + nf;
                int lam = lane ^ (nt & 15);
                int idx = (((bfc * 2 + kst) * 16 + nt) * 32 + lam) * 2;
                uint2 h = *(const uint2*)&Bh[idx];
                uint2 l = *(const uint2*)&Bl[idx];
                Bf [nf][0] = h.x; Bf [nf][1] = h.y;
                Bfl[nf][0] = l.x; Bfl[nf][1] = l.y;
            }
            #pragma unroll
            for (int mf = 0; mf < 2; mf++)
                #pragma unroll
                for (int nf = 0; nf < 4; nf++) {
                    MMA8(acc[mf][nf], Af[mf],  Bf[nf]);
                    MMA8(acc[mf][nf], Af[mf],  Bfl[nf]);
                    MMA8(acc[mf][nf], Afl[mf], Bf[nf]);
                }
        }
        __syncthreads();
    }

    #pragma unroll
    for (int mf = 0; mf < 2; mf++) {
        int row0 = m0 + wm * 32 + mf * 16 + lg;
        #pragma unroll
        for (int nf = 0; nf < 4; nf++) {
            int col = n0 + wn * 32 + nf * 8 + lt * 2;
            *(float2*)(P + (size_t)row0 * H2_ + col)       = make_float2(acc[mf][nf][0], acc[mf][nf][1]);
            *(float2*)(P + (size_t)(row0 + 8) * H2_ + col) = make_float2(acc[mf][nf][2], acc[mf][nf][3]);
        }
    }
}

// ---------------------------------------------------------------------------
// GEMM2 via 3xTF32 HMMA (proven R9): Q[head][ks] = relu(sum_j H_j + b1) @ W2.
// Block: 64x128 tile, K=64 slice (4 chunks), 256 thr, 8 warps (2Mx4N, 32x32),
// double-buffered. grid 128 = 2 heads x 8 M x 8 K.
// ---------------------------------------------------------------------------
__global__ __launch_bounds__(256) void k_gemm2_mma(
    const float* __restrict__ b1mu, const float* __restrict__ b1lv,
    const float* __restrict__ W2mu, const float* __restrict__ W2lv)
{
    __shared__ __align__(16) float Ah[2 * 2 * 4 * 32 * 4];
    __shared__ __align__(16) float Al[2 * 2 * 4 * 32 * 4];
    __shared__ __align__(16) float Bh[2 * 2 * 16 * 32 * 2];
    __shared__ __align__(16) float Bl[2 * 2 * 16 * 32 * 2];

    const int b    = blockIdx.x;
    const int head = b & 1;
    const int ks   = (b >> 1) & 7;
    const int m0   = (b >> 4) * 64;
    const int kb   = ks * 64;
    const float* Hb = &g_H[head][0][0];
    const float* b1 = head ? b1lv : b1mu;
    const float* W  = head ? W2lv : W2mu;
    float*       Q  = g_Q[head][ks];
    const size_t HS = (size_t)B_ * H2_;

    const int tid  = threadIdx.x;
    const int wid  = tid >> 5;
    const int lane = tid & 31;
    const int wm   = wid >> 2;
    const int wn   = wid & 3;
    const int lg   = lane >> 2;
    const int lt   = lane & 3;

    const int ar = tid >> 2, akq = tid & 3;
    const int akst = akq >> 1, akh = akq & 1;
    const int amt = ar >> 4, ag = ar & 7, arh = (ar >> 3) & 1;
    const size_t aoff = (size_t)(m0 + ar) * H2_ + kb + akq * 4;
    const int bkr = tid >> 4, bnq = tid & 15;
    const int bt  = bkr & 3, bkh = (bkr >> 2) & 1, bkst = bkr >> 3;
    const float* Wp = W + (size_t)(kb + bkr) * YD + bnq * 8;

    float acc[2][4][4] = {};
    float4 h0, h1, h2, h3, bv4, wb0, wb1;

    #define G2_LOAD(ch) do { \
        h0  = *(const float4*)(Hb + 0 * HS + aoff + (ch) * 16); \
        h1  = *(const float4*)(Hb + 1 * HS + aoff + (ch) * 16); \
        h2  = *(const float4*)(Hb + 2 * HS + aoff + (ch) * 16); \
        h3  = *(const float4*)(Hb + 3 * HS + aoff + (ch) * 16); \
        bv4 = *(const float4*)(b1 + kb + akq * 4 + (ch) * 16); \
        wb0 = *(const float4*)(Wp + (size_t)(ch) * 16 * YD + 0); \
        wb1 = *(const float4*)(Wp + (size_t)(ch) * 16 * YD + 4); \
    } while (0)

    #define G2_STAGE(bf) do { \
        float e[4]; \
        e[0] = fmaxf(h0.x + h1.x + h2.x + h3.x + bv4.x, 0.0f); \
        e[1] = fmaxf(h0.y + h1.y + h2.y + h3.y + bv4.y, 0.0f); \
        e[2] = fmaxf(h0.z + h1.z + h2.z + h3.z + bv4.z, 0.0f); \
        e[3] = fmaxf(h0.w + h1.w + h2.w + h3.w + bv4.w, 0.0f); \
        _Pragma("unroll") \
        for (int q = 0; q < 4; q++) { \
            float hi = tf32r(e[q]), lo = e[q] - hi; \
            int lam = (ag * 4 + q) ^ (akst | (ag & 2)); \
            int idx = (((((bf) * 2 + akst) * 4 + amt) * 32 + lam) * 4) + (arh + 2 * akh); \
            Ah[idx] = hi; Al[idx] = lo; \
        } \
        _Pragma("unroll") \
        for (int nh = 0; nh < 2; nh++) { \
            float4 v = nh ? wb1 : wb0; \
            float f[4] = {v.x, v.y, v.z, v.w}; \
            _Pragma("unroll") \
            for (int q = 0; q < 4; q++) { \
                float hi = tf32r(f[q]), lo = f[q] - hi; \
                int gg  = nh * 4 + q; \
                int lam = (gg * 4 + bt) ^ (bnq & 15); \
                int idx = (((((bf) * 2 + bkst) * 16 + bnq) * 32 + lam) * 2) + bkh; \
                Bh[idx] = hi; Bl[idx] = lo; \
            } \
        } \
    } while (0)

    G2_LOAD(0);
    G2_STAGE(0);
    G2_LOAD(1);
    __syncthreads();

    for (int ch = 0; ch < 4; ch++) {
        const int bfc = ch & 1;
        if (ch + 1 < 4) G2_STAGE((ch + 1) & 1);
        if (ch + 2 < 4) G2_LOAD(ch + 2);

        #pragma unroll
        for (int kst = 0; kst < 2; kst++) {
            uint32_t Af[2][4], Afl[2][4];
            #pragma unroll
            for (int mf = 0; mf < 2; mf++) {
                int mt  = wm * 2 + mf;
                int lam = lane ^ (kst | ((lane >> 2) & 2));
                int idx = (((bfc * 2 + kst) * 4 + mt) * 32 + lam) * 4;
                uint4 h = *(const uint4*)&Ah[idx];
                uint4 l = *(const uint4*)&Al[idx];
                Af [mf][0] = h.x; Af [mf][1] = h.y; Af [mf][2] = h.z; Af [mf][3] = h.w;
                Afl[mf][0] = l.x; Afl[mf][1] = l.y; Afl[mf][2] = l.z; Afl[mf][3] = l.w;
            }
            uint32_t Bf[4][2], Bfl[4][2];
            #pragma unroll
            for (int nf = 0; nf < 4; nf++) {
                int nt  = wn * 4 + nf;
                int lam = lane ^ (nt & 15);
                int idx = (((bfc * 2 + kst) * 16 + nt) * 32 + lam) * 2;
                uint2 h = *(const uint2*)&Bh[idx];
                uint2 l = *(const uint2*)&Bl[idx];
                Bf [nf][0] = h.x; Bf [nf][1] = h.y;
                Bfl[nf][0] = l.x; Bfl[nf][1] = l.y;
            }
            #pragma unroll
            for (int mf = 0; mf < 2; mf++)
                #pragma unroll
                for (int nf = 0; nf < 4; nf++) {
                    MMA8(acc[mf][nf], Af[mf],  Bf[nf]);
                    MMA8(acc[mf][nf], Af[mf],  Bfl[nf]);
                    MMA8(acc[mf][nf], Afl[mf], Bf[nf]);
                }
        }
        __syncthreads();
    }

    #pragma unroll
    for (int mf = 0; mf < 2; mf++) {
        int row0 = m0 + wm * 32 + mf * 16 + lg;
        #pragma unroll
        for (int nf = 0; nf < 4; nf++) {
            int col = (wn * 4 + nf) * 8 + lt * 2;
            *(float2*)(Q + (size_t)row0 * YD + col)       = make_float2(acc[mf][nf][0], acc[mf][nf][1]);
            *(float2*)(Q + (size_t)(row0 + 8) * YD + col) = make_float2(acc[mf][nf][2], acc[mf][nf][3]);
        }
    }
}

// ---------------------------------------------------------------------------
// Kernel C: epilogue + per-row reductions + final scalar (last-block ticket).
// negative == all_probs exactly in fp32 (511 + e^-20 == 511; log(B-1) cancels)
// ---------------------------------------------------------------------------
__global__ __launch_bounds__(128) void k_rows_final(
    const float* __restrict__ Y,
    const float* __restrict__ b2mu, const float* __restrict__ b2lv,
    float* __restrict__ out, int out_size)
{
    __shared__ double sSy[YD];
    __shared__ double sSy2[YD];
    __shared__ bool s_last;

    const int tid = threadIdx.x;
    {
        double s = 0.0, s2 = 0.0;
        #pragma unroll
        for (int p = 0; p < NPART; p++) { s += g_SyP[p][tid]; s2 += g_Sy2P[p][tid]; }
        sSy[tid] = s; sSy2[tid] = s2;
    }
    __syncthreads();

    const int lane = tid & 31;
    const int wid  = tid >> 5;
    const int i    = blockIdx.x * 4 + wid;

    double pos = 0.0, row = 0.0;
    #pragma unroll
    for (int q = 0; q < 4; q++) {
        int d = q * 32 + lane;
        int idx = i * YD + d;
        float muf = b2mu[d];
        float sf  = b2lv[d];
        #pragma unroll
        for (int j = 0; j < KS2; j++) {
            muf += g_Q[0][j][idx];
            sf  += g_Q[1][j][idx];
        }
        float lvf = tanhf(sf);
        float ivf = expf(-lvf);
        float yf  = Y[idx];

        float dmy = muf - yf;
        pos += (double)fmaf(-0.5f * dmy * dmy, ivf, -0.5f * lvf);

        double mu = (double)muf;
        double tq = fma(mu, fma(512.0, mu, -2.0 * sSy[d]), sSy2[d]);
        row = fma(-0.5 * (double)ivf, tq, row);
        row = fma(-256.0, (double)lvf, row);
    }
    #pragma unroll
    for (int off = 16; off > 0; off >>= 1) {
        pos += __shfl_down_sync(0xffffffffu, pos, off);
        row += __shfl_down_sync(0xffffffffu, row, off);
    }
    if (lane == 0) {
        g_pos_row[i] = pos;
        g_all_row[i] = row;
        __threadfence();
    }
    __syncthreads();

    if (tid == 0) {
        unsigned old = atomicAdd(&g_ctr, 1u);
        s_last = (old == gridDim.x - 1);
    }
    __syncthreads();
    if (!s_last) return;

    double p0 = 0.0, a0 = 0.0;
    #pragma unroll
    for (int j = tid; j < B_; j += 128) { p0 += g_pos_row[j]; a0 += g_all_row[j]; }
    sSy[tid]  = p0;
    sSy2[tid] = a0;
    __syncthreads();
    #pragma unroll
    for (int s = 64; s > 0; s >>= 1) {
        if (tid < s) { sSy[tid] += sSy[tid + s]; sSy2[tid] += sSy2[tid + s]; }
        __syncthreads();
    }
    if (tid == 0) {
        out[0] = (float)(sSy[0] / 512.0 - sSy2[0] / (512.0 * 512.0));
        g_ctr = 0;
    }
    for (int k = tid + 1; k < out_size; k += 128) out[k] = 0.0f;
}

// ---------------------------------------------------------------------------
extern "C" void kernel_launch(void* const* d_in, const int* in_sizes, int n_in,
                              void* d_out, int out_size)
{
    const float* x   = (const float*)d_in[0];
    const float* y   = (const float*)d_in[1];
    const float* w1m = (const float*)d_in[2];
    const float* b1m = (const float*)d_in[3];
    const float* w2m = (const float*)d_in[4];
    const float* b2m = (const float*)d_in[5];
    const float* w1l = (const float*)d_in[6];
    const float* b1l = (const float*)d_in[7];
    const float* w2l = (const float*)d_in[8];
    const float* b2l = (const float*)d_in[9];

    static int smem_set = 0;
    if (!smem_set) {
        cudaFuncSetAttribute(k_gemm1_mma, cudaFuncAttributeMaxDynamicSharedMemorySize, 65536);
        smem_set = 1;
    }

    k_gemm1_mma<<<128 + NPART, 512, 65536>>>(x, y, w1m, w1l);
    k_gemm2_mma<<<128, 256>>>(b1m, b1l, w2m, w2l);
    k_rows_final<<<B_ / 4, 128>>>(y, b2m, b2l, (float*)d_out, out_size);
}

// round 11
// speedup vs baseline: 1.1746x; 1.1746x over previous
#include <cuda_runtime.h>
#include <cuda_fp16.h>
#include <math.h>
#include <stdint.h>

#define B_  512
#define XD  768
#define YD  128
#define H2_ 512
#define NPART 16
#define KS1 4          // gemm1 K-split (768/4 = 192)
#define KS2 8          // gemm2 K-split (512/8 = 64)

typedef unsigned long long u64;

__device__ float  g_H[2][KS1][B_ * H2_];   // gemm1 raw partials
__device__ float  g_Q[2][KS2][B_ * YD];    // gemm2 raw partials
__device__ double g_SyP [NPART][YD];
__device__ double g_Sy2P[NPART][YD];
__device__ double g_pos_row[B_];
__device__ double g_all_row[B_];
__device__ unsigned int g_ctr = 0;

// ---------------- fp16 2-term split helpers ----------------
// x = h + l with h = fp16(x) (11 bits), l = fp16(x - h) (11 more bits).
// 3-product MMA (hh'+hl'+lh') then matches tf32-3x precision (~2^-21).
__device__ __forceinline__ void split_pack(float x0, float x1,
                                           uint32_t &hi, uint32_t &lo) {
    __half h0 = __float2half_rn(x0), h1 = __float2half_rn(x1);
    float r0 = x0 - __half2float(h0), r1 = x1 - __half2float(h1);
    __half l0 = __float2half_rn(r0), l1 = __float2half_rn(r1);
    __half2 H = __halves2half2(h0, h1), L = __halves2half2(l0, l1);
    hi = *(uint32_t*)&H; lo = *(uint32_t*)&L;
}

// D(16x8,f32) += A(16x16,f16) * B(16x8,f16)
#define MMA16(c, A, B) \
    asm volatile("mma.sync.aligned.m16n8k16.row.col.f32.f16.f16.f32 " \
        "{%0,%1,%2,%3},{%4,%5,%6,%7},{%8,%9},{%0,%1,%2,%3};" \
        : "+f"((c)[0]), "+f"((c)[1]), "+f"((c)[2]), "+f"((c)[3]) \
        : "r"((A)[0]), "r"((A)[1]), "r"((A)[2]), "r"((A)[3]), \
          "r"((B)[0]), "r"((B)[1]))

// fragment smem strides (u32 units), +33 padding vs 32 to spread banks
#define APITCH 33
// A slot s of frag = rowhalf + 2*khalf; B slot = khalf. lane = 4*lg + lt.

// ---------------------------------------------------------------------------
// Kernel A: blocks 0..127 = GEMM1 partials via 3x-fp16 HMMA m16n8k16.
//           blocks 128..143 = y column stats.
// Block: 128x128 tile, K=192 slice, 12 chunks of k16, 512 thr, 16 warps
// (4M x 4N, warp tile 32x32). Double-buffered, one sync per chunk.
// ---------------------------------------------------------------------------
__global__ __launch_bounds__(512) void k_gemm1_mma(
    const float* __restrict__ X, const float* __restrict__ Y,
    const float* __restrict__ Wmu, const float* __restrict__ Wlv)
{
    const int b = blockIdx.x;
    if (b >= 128) {
        const int p = b - 128;
        const int d = threadIdx.x;
        if (d < YD) {
            const int j0 = p * (B_ / NPART);
            double sy0 = 0, sy1 = 0, s20 = 0, s21 = 0;
            #pragma unroll 4
            for (int j = j0; j < j0 + B_ / NPART; j += 2) {
                double v0 = (double)Y[j * YD + d], v1 = (double)Y[(j + 1) * YD + d];
                sy0 += v0; s20 = fma(v0, v0, s20);
                sy1 += v1; s21 = fma(v1, v1, s21);
            }
            g_SyP[p][d] = sy0 + sy1; g_Sy2P[p][d] = s20 + s21;
        }
        return;
    }

    // A: [2buf][8mt][4slot][33], B: [2buf][16nt][2slot][33]
    __shared__ uint32_t Ah[2 * 8 * 4 * APITCH], Al[2 * 8 * 4 * APITCH];
    __shared__ uint32_t Bh[2 * 16 * 2 * APITCH], Bl[2 * 16 * 2 * APITCH];

    const int head = b & 1;
    const int ks   = (b >> 1) & 3;
    const int t4   = b >> 3;               // 0..15
    const int m0   = (t4 >> 2) * 128;
    const int n0   = (t4 & 3) * 128;
    const int kb   = ks * 192;
    const float* W = head ? Wlv : Wmu;
    float* P       = &g_H[head][ks][0];

    const int tid  = threadIdx.x;
    const int wid  = tid >> 5;
    const int lane = tid & 31;
    const int wm   = wid >> 2;             // 0..3
    const int wn   = wid & 3;              // 0..3
    const int lg   = lane >> 2;
    const int lt   = lane & 3;

    // A loader: ar = tid>>2 (row 0..127), akq = tid&3 (k-quad)
    const int ar = tid >> 2, akq = tid & 3;
    const int a_mt   = ar >> 4;
    const int a_slot = ((ar >> 3) & 1) + 2 * (akq >> 1);
    const int a_lane = 4 * (ar & 7) + 2 * (akq & 1);
    const float* Xp = X + (size_t)(m0 + ar) * XD + kb + akq * 4;
    // B loader: bkp = tid>>6 (k-pair 0..7), bn2 = tid&63 (n-pair)
    const int bkp = tid >> 6, bn2 = tid & 63;
    const int b_lt = bkp & 3, b_slot = bkp >> 2;
    const float* Wp = W + (size_t)(kb + 2 * bkp) * H2_ + n0 + 2 * bn2;

    float acc[2][4][4] = {};
    float4 xa; float2 w0, w1;

    #define G1_LOAD(ch) do { \
        xa = *(const float4*)(Xp + (ch) * 16); \
        w0 = *(const float2*)(Wp + (size_t)(ch) * 16 * H2_); \
        w1 = *(const float2*)(Wp + (size_t)(ch) * 16 * H2_ + H2_); \
    } while (0)

    #define G1_STAGE(bf) do { \
        uint32_t h01, l01, h23, l23; \
        split_pack(xa.x, xa.y, h01, l01); \
        split_pack(xa.z, xa.w, h23, l23); \
        int aidx = (((bf) * 8 + a_mt) * 4 + a_slot) * APITCH + a_lane; \
        Ah[aidx] = h01; Ah[aidx + 1] = h23; \
        Al[aidx] = l01; Al[aidx + 1] = l23; \
        _Pragma("unroll") \
        for (int j = 0; j < 2; j++) { \
            int n = 2 * bn2 + j; \
            float vk0 = j ? w0.y : w0.x; \
            float vk1 = j ? w1.y : w1.x; \
            uint32_t bhv, blv; \
            split_pack(vk0, vk1, bhv, blv); \
            int bidx = (((bf) * 16 + (n >> 3)) * 2 + b_slot) * APITCH \
                     + 4 * (n & 7) + b_lt; \
            Bh[bidx] = bhv; Bl[bidx] = blv; \
        } \
    } while (0)

    G1_LOAD(0);
    G1_STAGE(0);
    G1_LOAD(1);
    __syncthreads();

    for (int ch = 0; ch < 12; ch++) {
        const int bfc = ch & 1;
        if (ch + 1 < 12) G1_STAGE((ch + 1) & 1);
        if (ch + 2 < 12) G1_LOAD(ch + 2);

        uint32_t Af[2][4], Afl[2][4];
        #pragma unroll
        for (int mf = 0; mf < 2; mf++) {
            int mt = wm * 2 + mf;
            int base = ((bfc * 8 + mt) * 4) * APITCH + lane;
            #pragma unroll
            for (int s = 0; s < 4; s++) {
                Af [mf][s] = Ah[base + s * APITCH];
                Afl[mf][s] = Al[base + s * APITCH];
            }
        }
        uint32_t Bf[4][2], Bfl[4][2];
        #pragma unroll
        for (int nf = 0; nf < 4; nf++) {
            int nt = wn * 4 + nf;
            int base = ((bfc * 16 + nt) * 2) * APITCH + lane;
            #pragma unroll
            for (int s = 0; s < 2; s++) {
                Bf [nf][s] = Bh[base + s * APITCH];
                Bfl[nf][s] = Bl[base + s * APITCH];
            }
        }
        #pragma unroll
        for (int mf = 0; mf < 2; mf++)
            #pragma unroll
            for (int nf = 0; nf < 4; nf++) {
                MMA16(acc[mf][nf], Af[mf],  Bf[nf]);
                MMA16(acc[mf][nf], Af[mf],  Bfl[nf]);
                MMA16(acc[mf][nf], Afl[mf], Bf[nf]);
            }
        __syncthreads();
    }

    #pragma unroll
    for (int mf = 0; mf < 2; mf++) {
        int row0 = m0 + wm * 32 + mf * 16 + lg;
        #pragma unroll
        for (int nf = 0; nf < 4; nf++) {
            int col = n0 + wn * 32 + nf * 8 + lt * 2;
            *(float2*)(P + (size_t)row0 * H2_ + col)       = make_float2(acc[mf][nf][0], acc[mf][nf][1]);
            *(float2*)(P + (size_t)(row0 + 8) * H2_ + col) = make_float2(acc[mf][nf][2], acc[mf][nf][3]);
        }
    }
}

// ---------------------------------------------------------------------------
// GEMM2 via 3x-fp16 HMMA: Q[head][ks] = relu(sum_j H_j + b1) @ W2[kslice].
// Block: 64x128 tile, K=64 slice (4 chunks of k16), 256 thr, 8 warps
// (2M x 4N, warp tile 32x32), double-buffered. grid 128 = 2 x 8 M x 8 K.
// ---------------------------------------------------------------------------
__global__ __launch_bounds__(256) void k_gemm2_mma(
    const float* __restrict__ b1mu, const float* __restrict__ b1lv,
    const float* __restrict__ W2mu, const float* __restrict__ W2lv)
{
    // A: [2buf][4mt][4slot][33], B: [2buf][16nt][2slot][33]
    __shared__ uint32_t Ah[2 * 4 * 4 * APITCH], Al[2 * 4 * 4 * APITCH];
    __shared__ uint32_t Bh[2 * 16 * 2 * APITCH], Bl[2 * 16 * 2 * APITCH];

    const int b    = blockIdx.x;
    const int head = b & 1;
    const int ks   = (b >> 1) & 7;
    const int m0   = (b >> 4) * 64;
    const int kb   = ks * 64;
    const float* Hb = &g_H[head][0][0];
    const float* b1 = head ? b1lv : b1mu;
    const float* W  = head ? W2lv : W2mu;
    float*       Q  = g_Q[head][ks];
    const size_t HS = (size_t)B_ * H2_;

    const int tid  = threadIdx.x;
    const int wid  = tid >> 5;
    const int lane = tid & 31;
    const int wm   = wid >> 2;             // 0..1
    const int wn   = wid & 3;              // 0..3
    const int lg   = lane >> 2;
    const int lt   = lane & 3;

    // A loader: ar = tid>>2 (0..63), akq = tid&3
    const int ar = tid >> 2, akq = tid & 3;
    const int a_mt   = ar >> 4;            // 0..3
    const int a_slot = ((ar >> 3) & 1) + 2 * (akq >> 1);
    const int a_lane = 4 * (ar & 7) + 2 * (akq & 1);
    const size_t aoff = (size_t)(m0 + ar) * H2_ + kb + akq * 4;
    // B loader: bkp = tid>>5 (0..7), bn2u = (tid&31) + 32u (two units)
    const int bkp = tid >> 5, bn2b = tid & 31;
    const int b_lt = bkp & 3, b_slot = bkp >> 2;
    const float* Wp = W + (size_t)(kb + 2 * bkp) * YD;

    float acc[2][4][4] = {};
    float4 h0, h1, h2, h3, bv4;
    float2 wu0[2], wu1[2];

    #define G2_LOAD(ch) do { \
        h0  = *(const float4*)(Hb + 0 * HS + aoff + (ch) * 16); \
        h1  = *(const float4*)(Hb + 1 * HS + aoff + (ch) * 16); \
        h2  = *(const float4*)(Hb + 2 * HS + aoff + (ch) * 16); \
        h3  = *(const float4*)(Hb + 3 * HS + aoff + (ch) * 16); \
        bv4 = *(const float4*)(b1 + kb + akq * 4 + (ch) * 16); \
        _Pragma("unroll") \
        for (int u = 0; u < 2; u++) { \
            int n = 2 * (bn2b + 32 * u); \
            wu0[u] = *(const float2*)(Wp + (size_t)(ch) * 16 * YD + n); \
            wu1[u] = *(const float2*)(Wp + (size_t)(ch) * 16 * YD + YD + n); \
        } \
    } while (0)

    #define G2_STAGE(bf) do { \
        float e0 = fmaxf(h0.x + h1.x + h2.x + h3.x + bv4.x, 0.0f); \
        float e1 = fmaxf(h0.y + h1.y + h2.y + h3.y + bv4.y, 0.0f); \
        float e2 = fmaxf(h0.z + h1.z + h2.z + h3.z + bv4.z, 0.0f); \
        float e3 = fmaxf(h0.w + h1.w + h2.w + h3.w + bv4.w, 0.0f); \
        uint32_t h01, l01, h23, l23; \
        split_pack(e0, e1, h01, l01); \
        split_pack(e2, e3, h23, l23); \
        int aidx = (((bf) * 4 + a_mt) * 4 + a_slot) * APITCH + a_lane; \
        Ah[aidx] = h01; Ah[aidx + 1] = h23; \
        Al[aidx] = l01; Al[aidx + 1] = l23; \
        _Pragma("unroll") \
        for (int u = 0; u < 2; u++) { \
            _Pragma("unroll") \
            for (int j = 0; j < 2; j++) { \
                int n = 2 * (bn2b + 32 * u) + j; \
                float vk0 = j ? wu0[u].y : wu0[u].x; \
                float vk1 = j ? wu1[u].y : wu1[u].x; \
                uint32_t bhv, blv; \
                split_pack(vk0, vk1, bhv, blv); \
                int bidx = (((bf) * 16 + (n >> 3)) * 2 + b_slot) * APITCH \
                         + 4 * (n & 7) + b_lt; \
                Bh[bidx] = bhv; Bl[bidx] = blv; \
            } \
        } \
    } while (0)

    G2_LOAD(0);
    G2_STAGE(0);
    G2_LOAD(1);
    __syncthreads();

    for (int ch = 0; ch < 4; ch++) {
        const int bfc = ch & 1;
        if (ch + 1 < 4) G2_STAGE((ch + 1) & 1);
        if (ch + 2 < 4) G2_LOAD(ch + 2);

        uint32_t Af[2][4], Afl[2][4];
        #pragma unroll
        for (int mf = 0; mf < 2; mf++) {
            int mt = wm * 2 + mf;
            int base = ((bfc * 4 + mt) * 4) * APITCH + lane;
            #pragma unroll
            for (int s = 0; s < 4; s++) {
                Af [mf][s] = Ah[base + s * APITCH];
                Afl[mf][s] = Al[base + s * APITCH];
            }
        }
        uint32_t Bf[4][2], Bfl[4][2];
        #pragma unroll
        for (int nf = 0; nf < 4; nf++) {
            int nt = wn * 4 + nf;
            int base = ((bfc * 16 + nt) * 2) * APITCH + lane;
            #pragma unroll
            for (int s = 0; s < 2; s++) {
                Bf [nf][s] = Bh[base + s * APITCH];
                Bfl[nf][s] = Bl[base + s * APITCH];
            }
        }
        #pragma unroll
        for (int mf = 0; mf < 2; mf++)
            #pragma unroll
            for (int nf = 0; nf < 4; nf++) {
                MMA16(acc[mf][nf], Af[mf],  Bf[nf]);
                MMA16(acc[mf][nf], Af[mf],  Bfl[nf]);
                MMA16(acc[mf][nf], Afl[mf], Bf[nf]);
            }
        __syncthreads();
    }

    #pragma unroll
    for (int mf = 0; mf < 2; mf++) {
        int row0 = m0 + wm * 32 + mf * 16 + lg;
        #pragma unroll
        for (int nf = 0; nf < 4; nf++) {
            int col = (wn * 4 + nf) * 8 + lt * 2;
            *(float2*)(Q + (size_t)row0 * YD + col)       = make_float2(acc[mf][nf][0], acc[mf][nf][1]);
            *(float2*)(Q + (size_t)(row0 + 8) * YD + col) = make_float2(acc[mf][nf][2], acc[mf][nf][3]);
        }
    }
}

// ---------------------------------------------------------------------------
// Kernel C: epilogue + per-row reductions + final scalar (last-block ticket).
// negative == all_probs exactly in fp32 (511 + e^-20 == 511; log(B-1) cancels)
// ---------------------------------------------------------------------------
__global__ __launch_bounds__(128) void k_rows_final(
    const float* __restrict__ Y,
    const float* __restrict__ b2mu, const float* __restrict__ b2lv,
    float* __restrict__ out, int out_size)
{
    __shared__ double sSy[YD];
    __shared__ double sSy2[YD];
    __shared__ bool s_last;

    const int tid = threadIdx.x;
    {
        double s = 0.0, s2 = 0.0;
        #pragma unroll
        for (int p = 0; p < NPART; p++) { s += g_SyP[p][tid]; s2 += g_Sy2P[p][tid]; }
        sSy[tid] = s; sSy2[tid] = s2;
    }
    __syncthreads();

    const int lane = tid & 31;
    const int wid  = tid >> 5;
    const int i    = blockIdx.x * 4 + wid;

    double pos = 0.0, row = 0.0;
    #pragma unroll
    for (int q = 0; q < 4; q++) {
        int d = q * 32 + lane;
        int idx = i * YD + d;
        float muf = b2mu[d];
        float sf  = b2lv[d];
        #pragma unroll
        for (int j = 0; j < KS2; j++) {
            muf += g_Q[0][j][idx];
            sf  += g_Q[1][j][idx];
        }
        float lvf = tanhf(sf);
        float ivf = expf(-lvf);
        float yf  = Y[idx];

        float dmy = muf - yf;
        pos += (double)fmaf(-0.5f * dmy * dmy, ivf, -0.5f * lvf);

        double mu = (double)muf;
        double tq = fma(mu, fma(512.0, mu, -2.0 * sSy[d]), sSy2[d]);
        row = fma(-0.5 * (double)ivf, tq, row);
        row = fma(-256.0, (double)lvf, row);
    }
    #pragma unroll
    for (int off = 16; off > 0; off >>= 1) {
        pos += __shfl_down_sync(0xffffffffu, pos, off);
        row += __shfl_down_sync(0xffffffffu, row, off);
    }
    if (lane == 0) {
        g_pos_row[i] = pos;
        g_all_row[i] = row;
        __threadfence();
    }
    __syncthreads();

    if (tid == 0) {
        unsigned old = atomicAdd(&g_ctr, 1u);
        s_last = (old == gridDim.x - 1);
    }
    __syncthreads();
    if (!s_last) return;

    double p0 = 0.0, a0 = 0.0;
    #pragma unroll
    for (int j = tid; j < B_; j += 128) { p0 += g_pos_row[j]; a0 += g_all_row[j]; }
    sSy[tid]  = p0;
    sSy2[tid] = a0;
    __syncthreads();
    #pragma unroll
    for (int s = 64; s > 0; s >>= 1) {
        if (tid < s) { sSy[tid] += sSy[tid + s]; sSy2[tid] += sSy2[tid + s]; }
        __syncthreads();
    }
    if (tid == 0) {
        out[0] = (float)(sSy[0] / 512.0 - sSy2[0] / (512.0 * 512.0));
        g_ctr = 0;
    }
    for (int k = tid + 1; k < out_size; k += 128) out[k] = 0.0f;
}

// ---------------------------------------------------------------------------
extern "C" void kernel_launch(void* const* d_in, const int* in_sizes, int n_in,
                              void* d_out, int out_size)
{
    const float* x   = (const float*)d_in[0];
    const float* y   = (const float*)d_in[1];
    const float* w1m = (const float*)d_in[2];
    const float* b1m = (const float*)d_in[3];
    const float* w2m = (const float*)d_in[4];
    const float* b2m = (const float*)d_in[5];
    const float* w1l = (const float*)d_in[6];
    const float* b1l = (const float*)d_in[7];
    const float* w2l = (const float*)d_in[8];
    const float* b2l = (const float*)d_in[9];

    k_gemm1_mma<<<128 + NPART, 512>>>(x, y, w1m, w1l);
    k_gemm2_mma<<<128, 256>>>(b1m, b1l, w2m, w2l);
    k_rows_final<<<B_ / 4, 128>>>(y, b2m, b2l, (float*)d_out, out_size);
}